// round 17
// baseline (speedup 1.0000x reference)
#include <cuda_runtime.h>
#include <cstdint>
#include <cstddef>

// B=4, N=256, E=512. Persistent kernel: 740 CTAs (5/SM via
// __launch_bounds__(128,5)) x 128 threads. Static schedule, grid barriers:
//   P1: G(8 k64-planes) = X X^T            (640 jobs, nst=2)
//   P2: S(4 planes) = tril((sum8 G) Kw)    (240 jobs, nst<=2)
//   P3: T(4 planes) = tril((sum4 S) Qw^T)  (240 jobs, nst<=2)
//   P4: F(4 planes) = (sum4 T) X           (640 jobs, nst<=2)
//   P5: out = x*(1 + f - x.f), f = sum4 F  (1024 jobs)
// All jobs fully prefetch (cp.async B both stages + A register-sum both
// stages) then one wait + one sync + compute + store. tril masks at STORE
// only; plane tiles never written stay .bss zero, so plane-sums read exact
// zeros. Engine: mma.sync m16n8k16 bf16, 2-way split operands
// (D += Ah*Bh + Al*Bh + Ah*Bl), split accumulators, fp32 accum; hi/lo via
// packed cvt.rn.bf16x2 + ALU only. Deterministic static schedule.

#define NN_  256
#define EE_  512
#define GRID 740
#define GPLANE (4 * NN_ * NN_)
#define FPLANE (4 * NN_ * EE_)

typedef unsigned u32;

__device__ __align__(16) float g_G[8 * GPLANE];
__device__ __align__(16) float g_S[4 * GPLANE];
__device__ __align__(16) float g_T[4 * GPLANE];
__device__ __align__(16) float g_F[4 * FPLANE];

__device__ __align__(128) unsigned bar_cnt[64];
__device__ __align__(128) unsigned bar_gen[64];

__device__ __forceinline__ void grid_barrier(int idx) {
    __syncthreads();
    if (threadIdx.x == 0) {
        volatile unsigned* genp = &bar_gen[idx * 8];
        const unsigned g = *genp;
        __threadfence();
        if (atomicAdd(&bar_cnt[idx * 8], 1u) == GRID - 1) {
            bar_cnt[idx * 8] = 0;
            __threadfence();
            atomicAdd(&bar_gen[idx * 8], 1u);
        } else {
            while (*genp == g) { }
        }
        __threadfence();
    }
    __syncthreads();
}

// Split (v0, v1) -> packed bf16 hi pair + bf16 lo pair (v ~ hi + lo).
__device__ __forceinline__ void split2(float v0, float v1, u32& h, u32& l) {
    asm("cvt.rn.bf16x2.f32 %0, %1, %2;" : "=r"(h) : "f"(v1), "f"(v0));
    const float h0 = __uint_as_float(h << 16);
    const float h1 = __uint_as_float(h & 0xFFFF0000u);
    const float l0 = v0 - h0;
    const float l1 = v1 - h1;
    asm("cvt.rn.bf16x2.f32 %0, %1, %2;" : "=r"(l) : "f"(l1), "f"(l0));
}

__device__ __forceinline__ void mma_bf16(float* c, const u32* a, u32 b0, u32 b1) {
    asm("mma.sync.aligned.m16n8k16.row.col.f32.bf16.bf16.f32 "
        "{%0,%1,%2,%3},{%4,%5,%6,%7},{%8,%9},{%0,%1,%2,%3};"
        : "+f"(c[0]), "+f"(c[1]), "+f"(c[2]), "+f"(c[3])
        : "r"(a[0]), "r"(a[1]), "r"(a[2]), "r"(a[3]), "r"(b0), "r"(b1));
}

__device__ __forceinline__ void cp16(void* sdst, const void* gsrc) {
    const u32 d = (u32)__cvta_generic_to_shared(sdst);
    asm volatile("cp.async.cg.shared.global [%0], [%1], 16;" :: "r"(d), "l"(gsrc));
}

// One 32(M) x 64(N) tile, k in [kbase, kbase + nst*32), nst in {1,2}.
// A row-major [i][k] (lda), summed over ASUM part planes (stride aStride).
// NT: B[j][k] row-major (ldb); else B[k][j]. MASK_C: tril mask at store.
// 4 warps: wm = warp&1 (m16 half), wn = warp>>1 (n32 half; 4 n8 tiles).
// Whole job prefetched up front: one cp.async wait, one sync, compute.
template<bool NT, bool MASK_C, int ASUM>
__device__ __forceinline__ void tile_gemm(
    const float* __restrict__ A, int lda, size_t aStride,
    const float* __restrict__ B, int ldb,
    float* __restrict__ C, int ldc,
    int i0, int j0, int kbase, int nst,
    float (*As)[1152],     // [2][32 rows][36]
    float (*Bs)[2304])     // [2]; NT: [64 cols][36], NN: [32 k][72]
{
    const int tid  = threadIdx.x;
    const int lane = tid & 31;
    const int warp = tid >> 5;
    const int wm   = warp & 1;
    const int wn   = warp >> 1;
    const int g    = lane >> 2;
    const int t    = lane & 3;

    const int arow = tid >> 2;          // 0..31
    const int ac8  = (tid & 3) << 3;    // 0,8,16,24

    auto issueB = [&](int s) {
        const int kg = kbase + s * 32;
        float* slot = Bs[s];
        #pragma unroll
        for (int h = 0; h < 4; h++) {
            const int idx = tid + h * 128;
            if (NT) {
                const int col = idx >> 3, kk = (idx & 7) << 2;
                cp16(&slot[col * 36 + kk],
                     &B[(size_t)(j0 + col) * ldb + kg + kk]);
            } else {
                const int kr = idx >> 4, cc = (idx & 15) << 2;
                cp16(&slot[kr * 72 + cc],
                     &B[(size_t)(kg + kr) * ldb + j0 + cc]);
            }
        }
    };
    auto loadAsts = [&](int s) {
        const int kg = kbase + s * 32;
        #pragma unroll
        for (int it = 0; it < 2; it++) {
            const size_t off = (size_t)(i0 + arow) * lda + kg + ac8 + it * 4;
            float4 v = *(const float4*)&A[off];
            #pragma unroll
            for (int p = 1; p < ASUM; p++) {
                const float4 w = *(const float4*)&A[off + (size_t)p * aStride];
                v.x += w.x; v.y += w.y; v.z += w.z; v.w += w.w;
            }
            *(float4*)&As[s][arow * 36 + ac8 + it * 4] = v;
        }
    };

    float accP[4][4] = {};   // hi*hi + hi*lo
    float accQ[4][4] = {};   // lo*hi

    auto compute = [&](int s) {
        const float* Asl = As[s];
        const float* Bsl = Bs[s];
        #pragma unroll
        for (int kk = 0; kk < 32; kk += 16) {
            u32 ah[4], al[4];
            const int r0 = wm * 16 + g;
            const float2 a0 = *(const float2*)&Asl[r0 * 36 + kk + 2 * t];
            const float2 a1 = *(const float2*)&Asl[(r0 + 8) * 36 + kk + 2 * t];
            const float2 a2 = *(const float2*)&Asl[r0 * 36 + kk + 2 * t + 8];
            const float2 a3 = *(const float2*)&Asl[(r0 + 8) * 36 + kk + 2 * t + 8];
            split2(a0.x, a0.y, ah[0], al[0]);
            split2(a1.x, a1.y, ah[1], al[1]);
            split2(a2.x, a2.y, ah[2], al[2]);
            split2(a3.x, a3.y, ah[3], al[3]);
            #pragma unroll
            for (int u = 0; u < 4; u++) {
                const int col = wn * 32 + u * 8 + g;
                float2 q0, q1;
                if (NT) {
                    q0 = *(const float2*)&Bsl[col * 36 + kk + 2 * t];
                    q1 = *(const float2*)&Bsl[col * 36 + kk + 2 * t + 8];
                } else {
                    q0.x = Bsl[(kk + 2 * t) * 72 + col];
                    q0.y = Bsl[(kk + 2 * t + 1) * 72 + col];
                    q1.x = Bsl[(kk + 2 * t + 8) * 72 + col];
                    q1.y = Bsl[(kk + 2 * t + 9) * 72 + col];
                }
                u32 bh0, bl0, bh1, bl1;
                split2(q0.x, q0.y, bh0, bl0);
                split2(q1.x, q1.y, bh1, bl1);
                mma_bf16(accP[u], ah, bh0, bh1);   // hi*hi
                mma_bf16(accQ[u], al, bh0, bh1);   // lo*hi (indep chain)
                mma_bf16(accP[u], ah, bl0, bl1);   // hi*lo
            }
        }
    };

    // full-job prefetch
    issueB(0);
    if (nst > 1) issueB(1);
    asm volatile("cp.async.commit_group;");
    loadAsts(0);
    if (nst > 1) loadAsts(1);
    asm volatile("cp.async.wait_group 0;");
    __syncthreads();

    compute(0);
    if (nst > 1) compute(1);

    #pragma unroll
    for (int u = 0; u < 4; u++) {
        const int jb = j0 + wn * 32 + u * 8 + 2 * t;
        #pragma unroll
        for (int h = 0; h < 2; h++) {
            const int i = i0 + wm * 16 + g + h * 8;
            float c0 = accP[u][2 * h]     + accQ[u][2 * h];
            float c1 = accP[u][2 * h + 1] + accQ[u][2 * h + 1];
            if (MASK_C) {
                if (jb > i)     c0 = 0.f;
                if (jb + 1 > i) c1 = 0.f;
            }
            *(float2*)&C[(size_t)i * ldc + jb] = make_float2(c0, c1);
        }
    }
    __syncthreads();   // smem safe for next job
}

// 20 lower 32x64 tiles per 256x256 (band r 0..7; c*64 <= r*32+31)
__constant__ signed char t20_r[20] = {0,1,2,2,3,3,4,4,4,5,5,5,6,6,6,6,7,7,7,7};
__constant__ signed char t20_c[20] = {0,0,0,1,0,1,0,1,2,0,1,2,0,1,2,3,0,1,2,3};
// P4: (r, kp) pairs happen to share t20's (r, c) pattern; nst differs:
__constant__ signed char p4_n[20]  = {1,2,2,1,2,2,2,2,1,2,2,2,2,2,2,1,2,2,2,2};
// P2/P3 job table per batch: 60 entries (tile e, k-plane kp, nst)
__constant__ signed char p2_e[60] = {
    0, 1, 2,2, 3,3, 4,4, 5,5,
    6,6,6, 7,7,7, 8,8,8, 9,9,9, 10,10,10, 11,11,11,
    12,12,12,12, 13,13,13,13, 14,14,14,14, 15,15,15,15,
    16,16,16,16, 17,17,17,17, 18,18,18,18, 19,19,19,19};
__constant__ signed char p2_kp[60] = {
    0, 0, 0,1, 0,1, 0,1, 0,1,
    0,1,2, 0,1,2, 0,1,2, 0,1,2, 0,1,2, 0,1,2,
    0,1,2,3, 0,1,2,3, 0,1,2,3, 0,1,2,3,
    0,1,2,3, 0,1,2,3, 0,1,2,3, 0,1,2,3};
__constant__ signed char p2_n[60] = {
    1, 2, 2,1, 2,1, 2,2, 2,2,
    2,2,1, 2,2,1, 2,2,1, 2,2,2, 2,2,2, 2,2,2,
    2,2,2,1, 2,2,2,1, 2,2,2,1, 2,2,2,1,
    2,2,2,2, 2,2,2,2, 2,2,2,2, 2,2,2,2};

__global__ __launch_bounds__(128, 5)
void replicator_short(const float* __restrict__ X,
                      const float* __restrict__ Qw,
                      const float* __restrict__ Kw,
                      float* __restrict__ out)
{
    __shared__ float As[2][1152];   //  9.2 KB
    __shared__ float Bs[2][2304];   // 18.4 KB
    __shared__ float red[4];

    const int tid = threadIdx.x;
    const size_t sX = (size_t)NN_ * EE_;
    const size_t sG = (size_t)NN_ * NN_;

    // ---- P1: G planes(8, k64 each) = X X^T, 640 jobs (b x 20 x 8), nst=2
    for (int job = blockIdx.x; job < 640; job += GRID) {
        const int b  = job / 160;
        const int rm = job - b * 160;
        const int e  = rm >> 3;
        const int kp = rm & 7;
        tile_gemm<true, true, 1>(
            X + b * sX, EE_, 0, X + b * sX, EE_,
            g_G + (size_t)kp * GPLANE + b * sG, NN_,
            t20_r[e] * 32, t20_c[e] * 64, kp * 64, 2, As, Bs);
    }
    grid_barrier(0);

    // ---- P2: S planes(4) = tril( (sum8 G) Kw ), 240 jobs
    for (int job = blockIdx.x; job < 240; job += GRID) {
        const int b  = job / 60;
        const int en = job - b * 60;
        const int e  = p2_e[en];
        const int kp = p2_kp[en];
        tile_gemm<false, true, 8>(
            g_G + b * sG, NN_, (size_t)GPLANE, Kw, NN_,
            g_S + (size_t)kp * GPLANE + b * sG, NN_,
            t20_r[e] * 32, t20_c[e] * 64, kp * 64, p2_n[en], As, Bs);
    }
    grid_barrier(1);

    // ---- P3: T planes(4) = tril( (sum4 S) Qw^T ), 240 jobs
    for (int job = blockIdx.x; job < 240; job += GRID) {
        const int b  = job / 60;
        const int en = job - b * 60;
        const int e  = p2_e[en];
        const int kp = p2_kp[en];
        tile_gemm<true, true, 4>(
            g_S + b * sG, NN_, (size_t)GPLANE, Qw, NN_,
            g_T + (size_t)kp * GPLANE + b * sG, NN_,
            t20_r[e] * 32, t20_c[e] * 64, kp * 64, p2_n[en], As, Bs);
    }
    grid_barrier(2);

    // ---- P4: F planes(4) = (sum4 T) X, 640 jobs (b x 20 (r,kp) x 8 et)
    for (int job = blockIdx.x; job < 640; job += GRID) {
        const int b  = job / 160;
        const int rm = job - b * 160;
        const int bi = rm >> 3;
        const int et = rm & 7;
        const int r  = t20_r[bi];
        const int kp = t20_c[bi];
        tile_gemm<false, false, 4>(
            g_T + b * sG, NN_, (size_t)GPLANE, X + b * sX, EE_,
            g_F + (size_t)kp * FPLANE + b * sX, EE_,
            r * 32, et * 64, kp * 64, p4_n[bi], As, Bs);
    }
    grid_barrier(3);

    // ---- P5: epilogue, 1024 rows (f = sum of 4 F planes)
    for (int job = blockIdx.x; job < 1024; job += GRID) {
        const size_t base = (size_t)job * EE_;

        float4 x = *(const float4*)&X[base + tid * 4];
        float4 f = make_float4(0.f, 0.f, 0.f, 0.f);
        #pragma unroll
        for (int p = 0; p < 4; p++) {
            const float4 w =
                *(const float4*)&g_F[(size_t)p * FPLANE + base + tid * 4];
            f.x += w.x; f.y += w.y; f.z += w.z; f.w += w.w;
        }

        float sum = x.x * f.x + x.y * f.y + x.z * f.z + x.w * f.w;
        #pragma unroll
        for (int o = 16; o; o >>= 1)
            sum += __shfl_xor_sync(0xffffffffu, sum, o);

        if ((tid & 31) == 0) red[tid >> 5] = sum;
        __syncthreads();
        const float avg = red[0] + red[1] + red[2] + red[3];

        float4 o;
        o.x = x.x * (1.f + f.x - avg);
        o.y = x.y * (1.f + f.y - avg);
        o.z = x.z * (1.f + f.z - avg);
        o.w = x.w * (1.f + f.w - avg);
        *(float4*)&out[base + tid * 4] = o;
        __syncthreads();
    }
}

extern "C" void kernel_launch(void* const* d_in, const int* in_sizes, int n_in,
                              void* d_out, int out_size)
{
    const float* X  = (const float*)d_in[0];   // (4,256,512)
    const float* Qw = (const float*)d_in[1];   // (256,256)
    const float* Kw = (const float*)d_in[2];   // (256,256)
    float* out = (float*)d_out;                // (4,256,512)

    replicator_short<<<GRID, 128>>>(X, Qw, Kw, out);
}